// round 4
// baseline (speedup 1.0000x reference)
#include <cuda_runtime.h>
#include <cuda_bf16.h>
#include <cstdint>

// ---------------- Problem constants ----------------
#define BATCH   32
#define HW      56
#define CDIM    384
#define NH      12
#define DH      32
#define WS      7
#define T       49
#define NWIN    64
#define BN      (BATCH*NWIN)       // 2048
#define MROWS   (BN*T)             // 100352
#define NQKV    (3*CDIM)           // 1152
#define SCALE   0.17677669529663687f

// ---------------- Scratch (static device memory) ----------------
__device__ float          g_qkv[(size_t)BN * NH * 3 * T * DH];     // attn input, fp32
__device__ __nv_bfloat16  g_xw_hi[(size_t)MROWS * CDIM];
__device__ __nv_bfloat16  g_xw_lo[(size_t)MROWS * CDIM];
__device__ __nv_bfloat16  g_att_hi[(size_t)MROWS * CDIM];
__device__ __nv_bfloat16  g_att_lo[(size_t)MROWS * CDIM];
__device__ __nv_bfloat16  g_wq_hi[(size_t)NQKV * CDIM];
__device__ __nv_bfloat16  g_wq_lo[(size_t)NQKV * CDIM];
__device__ __nv_bfloat16  g_wp_hi[(size_t)CDIM * CDIM];
__device__ __nv_bfloat16  g_wp_lo[(size_t)CDIM * CDIM];

// ---------------- helpers ----------------
__device__ __forceinline__ uint32_t smem_u32(const void* p) {
    uint32_t a;
    asm("{ .reg .u64 t; cvta.to.shared.u64 t, %1; cvt.u32.u64 %0, t; }" : "=r"(a) : "l"(p));
    return a;
}

__device__ __forceinline__ void ldsm_x4(uint32_t& r0, uint32_t& r1, uint32_t& r2, uint32_t& r3,
                                        uint32_t addr) {
    asm volatile("ldmatrix.sync.aligned.m8n8.x4.shared.b16 {%0,%1,%2,%3}, [%4];"
                 : "=r"(r0), "=r"(r1), "=r"(r2), "=r"(r3) : "r"(addr));
}

__device__ __forceinline__ void mma_bf16(float* c, const uint32_t* a, uint32_t b0, uint32_t b1) {
    asm volatile(
        "mma.sync.aligned.m16n8k16.row.col.f32.bf16.bf16.f32 "
        "{%0,%1,%2,%3}, {%4,%5,%6,%7}, {%8,%9}, {%0,%1,%2,%3};"
        : "+f"(c[0]), "+f"(c[1]), "+f"(c[2]), "+f"(c[3])
        : "r"(a[0]), "r"(a[1]), "r"(a[2]), "r"(a[3]), "r"(b0), "r"(b1));
}

__device__ __forceinline__ void cp16(uint32_t dst, const void* src) {
    asm volatile("cp.async.cg.shared.global [%0], [%1], 16;" :: "r"(dst), "l"(src));
}

__device__ __forceinline__ void split_bf16(float v, __nv_bfloat16& h, __nv_bfloat16& l) {
    h = __float2bfloat16_rn(v);
    l = __float2bfloat16_rn(v - __bfloat162float(h));
}

// ---------------------------------------------------------------------------
// Precompute 1: gather x (roll -3, window partition) -> bf16 hi/lo [MROWS,384]
// ---------------------------------------------------------------------------
__global__ __launch_bounds__(256)
void gather_convert_x(const float* __restrict__ x)
{
    int idx = blockIdx.x * 256 + threadIdx.x;
    if (idx >= MROWS * (CDIM / 4)) return;
    int row = idx / (CDIM / 4);
    int c4  = idx % (CDIM / 4);
    int bn = row / T, t = row % T;
    int b = bn >> 6, win = bn & 63;
    int wr = win >> 3, wc = win & 7;
    int tr = t / WS, tc = t % WS;
    int h = wr * WS + tr + 3; if (h >= HW) h -= HW;
    int w = wc * WS + tc + 3; if (w >= HW) w -= HW;
    float4 v = *(const float4*)(x + ((size_t)((b * HW + h) * HW + w)) * CDIM + c4 * 4);
    __nv_bfloat16 h0,h1,h2,h3,l0,l1,l2,l3;
    split_bf16(v.x,h0,l0); split_bf16(v.y,h1,l1); split_bf16(v.z,h2,l2); split_bf16(v.w,h3,l3);
    size_t o = (size_t)row * CDIM + c4 * 4;
    *(__nv_bfloat162*)(g_xw_hi + o)     = __nv_bfloat162{h0,h1};
    *(__nv_bfloat162*)(g_xw_hi + o + 2) = __nv_bfloat162{h2,h3};
    *(__nv_bfloat162*)(g_xw_lo + o)     = __nv_bfloat162{l0,l1};
    *(__nv_bfloat162*)(g_xw_lo + o + 2) = __nv_bfloat162{l2,l3};
}

// ---------------------------------------------------------------------------
// Precompute 2: fp32 -> bf16 hi/lo (weights)
// ---------------------------------------------------------------------------
__global__ __launch_bounds__(256)
void convert_w(const float* __restrict__ src, __nv_bfloat16* __restrict__ hi,
               __nv_bfloat16* __restrict__ lo, int n4)
{
    int idx = blockIdx.x * 256 + threadIdx.x;
    if (idx >= n4) return;
    float4 v = *(const float4*)(src + (size_t)idx * 4);
    __nv_bfloat16 h0,h1,h2,h3,l0,l1,l2,l3;
    split_bf16(v.x,h0,l0); split_bf16(v.y,h1,l1); split_bf16(v.z,h2,l2); split_bf16(v.w,h3,l3);
    size_t o = (size_t)idx * 4;
    *(__nv_bfloat162*)(hi + o)     = __nv_bfloat162{h0,h1};
    *(__nv_bfloat162*)(hi + o + 2) = __nv_bfloat162{h2,h3};
    *(__nv_bfloat162*)(lo + o)     = __nv_bfloat162{l0,l1};
    *(__nv_bfloat162*)(lo + o + 2) = __nv_bfloat162{l2,l3};
}

// ---------------------------------------------------------------------------
// mma.sync GEMM, 2-stage cp.async pipeline.
// C[128,128] = A[128,384] @ B[128,384]^T  (bf16 hi/lo x3)
// 8 warps, warp tile 64x32 (warp grid 2x4), BK=32, padded smem stride 40.
// ---------------------------------------------------------------------------
#define SSTR       40                   // bf16 elems per smem row (80B, conflict-free mod 128)
#define TEN_BYTES  (128 * SSTR * 2)     // 10240 B per tensor
#define STG_BYTES  (4 * TEN_BYTES)      // 40960 B per stage
#define SMEM_DYN   (2 * STG_BYTES)      // 81920 B
#define NKIT       (CDIM / 32)          // 12

template<int MODE>
__global__ __launch_bounds__(256)
void gemm_mma(const float* __restrict__ bias, float* __restrict__ out)
{
    extern __shared__ __align__(16) char dynsmem[];
    const uint32_t u0 = smem_u32(dynsmem);

    const __nv_bfloat16* __restrict__ a_hi = (MODE == 0) ? g_xw_hi : g_att_hi;
    const __nv_bfloat16* __restrict__ a_lo = (MODE == 0) ? g_xw_lo : g_att_lo;
    const __nv_bfloat16* __restrict__ b_hi = (MODE == 0) ? g_wq_hi : g_wp_hi;
    const __nv_bfloat16* __restrict__ b_lo = (MODE == 0) ? g_wq_lo : g_wp_lo;

    const int tid  = threadIdx.x;
    const int lane = tid & 31;
    const int wid  = tid >> 5;
    const int wm   = wid & 1;
    const int wn   = wid >> 1;
    const int mbase = blockIdx.y * 128;
    const int nbase = blockIdx.x * 128;

    float acc[4][4][4];
    #pragma unroll
    for (int i = 0; i < 4; i++)
        #pragma unroll
        for (int j = 0; j < 4; j++)
            #pragma unroll
            for (int k = 0; k < 4; k++) acc[i][j][k] = 0.f;

    // gmem/smem line mapping: 512 16B-lines per tensor per chunk, 2 per thread
    const int r0g = tid >> 2, q0g = tid & 3;   // rows 0..63
    const int r1g = r0g + 64;                  // rows 64..127
    const int s0 = r0g * 80 + q0g * 16;        // smem byte offsets
    const int s1 = r1g * 80 + q0g * 16;

    auto issue = [&](int st, int k0) {
        uint32_t base = u0 + st * STG_BYTES;
        size_t a0 = (size_t)(mbase + r0g) * CDIM + k0 + q0g * 8;
        size_t a1 = a0 + (size_t)64 * CDIM;
        size_t b0 = (size_t)(nbase + r0g) * CDIM + k0 + q0g * 8;
        size_t b1 = b0 + (size_t)64 * CDIM;
        cp16(base + s0,                 a_hi + a0);
        cp16(base + s1,                 a_hi + a1);
        cp16(base + TEN_BYTES + s0,     a_lo + a0);
        cp16(base + TEN_BYTES + s1,     a_lo + a1);
        cp16(base + 2*TEN_BYTES + s0,   b_hi + b0);
        cp16(base + 2*TEN_BYTES + s1,   b_hi + b1);
        cp16(base + 3*TEN_BYTES + s0,   b_lo + b0);
        cp16(base + 3*TEN_BYTES + s1,   b_lo + b1);
        asm volatile("cp.async.commit_group;");
    };

    // ldmatrix lane addressing
    const int aRow = wm * 64 + (lane & 15);
    const int aCol = (lane >> 4) << 3;
    const int bRow = wn * 32 + (lane & 7) + (((lane >> 4) & 1) << 3);
    const int bCol = ((lane >> 3) & 1) << 3;

    issue(0, 0);

    for (int it = 0; it < NKIT; it++) {
        if (it + 1 < NKIT) {
            issue((it + 1) & 1, (it + 1) * 32);
            asm volatile("cp.async.wait_group 1;");
        } else {
            asm volatile("cp.async.wait_group 0;");
        }
        __syncthreads();

        const uint32_t uAh = u0 + (it & 1) * STG_BYTES;
        const uint32_t uAl = uAh + TEN_BYTES;
        const uint32_t uBh = uAh + 2 * TEN_BYTES;
        const uint32_t uBl = uAh + 3 * TEN_BYTES;

        #pragma unroll
        for (int ks = 0; ks < 2; ks++) {
            const uint32_t kOffB = (uint32_t)(ks * 32);  // 16 elems * 2B
            uint32_t ah[4][4], al[4][4];
            #pragma unroll
            for (int mt = 0; mt < 4; mt++) {
                uint32_t off = (uint32_t)(((aRow + mt * 16) * SSTR + aCol) * 2) + kOffB;
                ldsm_x4(ah[mt][0], ah[mt][1], ah[mt][2], ah[mt][3], uAh + off);
                ldsm_x4(al[mt][0], al[mt][1], al[mt][2], al[mt][3], uAl + off);
            }
            uint32_t bh[8], bl[8];
            #pragma unroll
            for (int nt2 = 0; nt2 < 2; nt2++) {
                uint32_t off = (uint32_t)(((bRow + nt2 * 16) * SSTR + bCol) * 2) + kOffB;
                ldsm_x4(bh[nt2*4+0], bh[nt2*4+1], bh[nt2*4+2], bh[nt2*4+3], uBh + off);
                ldsm_x4(bl[nt2*4+0], bl[nt2*4+1], bl[nt2*4+2], bl[nt2*4+3], uBl + off);
            }
            #pragma unroll
            for (int mt = 0; mt < 4; mt++)
                #pragma unroll
                for (int nt = 0; nt < 4; nt++) {
                    uint32_t B0h = bh[nt*2+0], B1h = bh[nt*2+1];
                    uint32_t B0l = bl[nt*2+0], B1l = bl[nt*2+1];
                    mma_bf16(acc[mt][nt], ah[mt], B0h, B1h);
                    mma_bf16(acc[mt][nt], ah[mt], B0l, B1l);
                    mma_bf16(acc[mt][nt], al[mt], B0h, B1h);
                }
        }
        __syncthreads();   // protect buffer (it&1) before issue at it+1 overwrites it at it+2
    }

    // ---- Epilogue ----
    #pragma unroll
    for (int mt = 0; mt < 4; mt++) {
        #pragma unroll
        for (int hf = 0; hf < 2; hf++) {
            int m = mbase + wm * 64 + mt * 16 + (lane >> 2) + hf * 8;
            int bn = m / T, t = m % T;
            if (MODE == 0) {
                #pragma unroll
                for (int nt = 0; nt < 4; nt++) {
                    int col = nbase + wn * 32 + nt * 8 + (lane & 3) * 2;
                    int which = col / CDIM;
                    int rem   = col - which * CDIM;
                    int head  = rem >> 5;
                    int d     = rem & 31;
                    float2 v;
                    v.x = acc[mt][nt][hf*2+0] + __ldg(&bias[col]);
                    v.y = acc[mt][nt][hf*2+1] + __ldg(&bias[col+1]);
                    *(float2*)(g_qkv + ((size_t)(bn * NH + head) * 3 + which) * (T * DH)
                               + t * DH + d) = v;
                }
            } else {
                int b = bn >> 6, win = bn & 63;
                int wr = win >> 3, wc = win & 7;
                int tr = t / WS, tc = t % WS;
                int h = wr * WS + tr + 3; if (h >= HW) h -= HW;
                int w = wc * WS + tc + 3; if (w >= HW) w -= HW;
                float* orow = out + ((size_t)((b * HW + h) * HW + w)) * CDIM;
                #pragma unroll
                for (int nt = 0; nt < 4; nt++) {
                    int col = nbase + wn * 32 + nt * 8 + (lane & 3) * 2;
                    float2 v;
                    v.x = acc[mt][nt][hf*2+0] + __ldg(&bias[col]);
                    v.y = acc[mt][nt][hf*2+1] + __ldg(&bias[col+1]);
                    *(float2*)(orow + col) = v;
                }
            }
        }
    }
}

// ---------------------------------------------------------------------------
// Attention: block per (window, head). Register-tiled 4x4, float4 LDS.
// ---------------------------------------------------------------------------
__global__ __launch_bounds__(256)
void attn_kernel(const float* __restrict__ table)
{
    const int bnh  = blockIdx.x;
    const int bn   = bnh / NH;
    const int head = bnh % NH;
    const int tid  = threadIdx.x;

    __shared__ __align__(16) float qT[32 * 52];
    __shared__ __align__(16) float kT[32 * 52];
    __shared__ __align__(16) float vs[49 * 32];
    __shared__ __align__(16) float S[52 * 52];
    __shared__ int rid[64];

    const float* base = g_qkv + (size_t)(bn * NH + head) * (3 * T * DH);
    for (int i = tid; i < 3 * T * DH; i += 256) {
        int sec = i / (T * DH);
        int rem = i - sec * (T * DH);
        int t = rem >> 5, d = rem & 31;
        float v = base[i];
        if      (sec == 0) qT[d * 52 + t] = v;
        else if (sec == 1) kT[d * 52 + t] = v;
        else               vs[t * 32 + d] = v;
    }
    if (tid < T) {
        int win = bn & 63;
        int wr = win >> 3, wc = win & 7;
        int tr = tid / WS, tc = tid % WS;
        int h = wr * WS + tr;
        int w = wc * WS + tc;
        int rh = (h < 49) ? 0 : ((h < 53) ? 1 : 2);
        int rw = (w < 49) ? 0 : ((w < 53) ? 1 : 2);
        rid[tid] = rh * 3 + rw;
    }
    __syncthreads();

    for (int task = tid; task < 169; task += 256) {
        int tb = task / 13, sbk = task % 13;
        float acc[4][4];
        #pragma unroll
        for (int i = 0; i < 4; i++)
            #pragma unroll
            for (int j = 0; j < 4; j++) acc[i][j] = 0.f;
        #pragma unroll
        for (int d = 0; d < 32; d++) {
            float4 qv = *(const float4*)&qT[d * 52 + tb * 4];
            float4 kv = *(const float4*)&kT[d * 52 + sbk * 4];
            float qa[4] = {qv.x, qv.y, qv.z, qv.w};
            float ka[4] = {kv.x, kv.y, kv.z, kv.w};
            #pragma unroll
            for (int i = 0; i < 4; i++)
                #pragma unroll
                for (int j = 0; j < 4; j++)
                    acc[i][j] = fmaf(qa[i], ka[j], acc[i][j]);
        }
        #pragma unroll
        for (int i = 0; i < 4; i++) {
            int t = tb * 4 + i;
            if (t >= T) break;
            int tr = t / WS, tcc = t % WS;
            #pragma unroll
            for (int j = 0; j < 4; j++) {
                int s = sbk * 4 + j;
                if (s >= T) continue;
                int sr = s / WS, sc = s % WS;
                float val = acc[i][j] * SCALE;
                int idx = (tr - sr + 6) * 13 + (tcc - sc + 6);
                val += __ldg(&table[idx * NH + head]);
                if (rid[t] != rid[s]) val -= 100.0f;
                S[t * 52 + s] = val;
            }
        }
    }
    __syncthreads();

    if (tid < T) {
        float mx = -1e30f;
        #pragma unroll 7
        for (int s = 0; s < T; s++) mx = fmaxf(mx, S[tid * 52 + s]);
        float sum = 0.f;
        #pragma unroll 7
        for (int s = 0; s < T; s++) {
            float e = __expf(S[tid * 52 + s] - mx);
            S[tid * 52 + s] = e;
            sum += e;
        }
        float inv = 1.0f / sum;
        #pragma unroll 7
        for (int s = 0; s < T; s++) S[tid * 52 + s] *= inv;
    }
    __syncthreads();

    for (int task = tid; task < 13 * 8; task += 256) {
        int tb = task / 8, db = task % 8;
        float acc[4][4];
        #pragma unroll
        for (int i = 0; i < 4; i++)
            #pragma unroll
            for (int j = 0; j < 4; j++) acc[i][j] = 0.f;
        for (int s = 0; s < T; s++) {
            float4 vv = *(const float4*)&vs[s * 32 + db * 4];
            float va[4] = {vv.x, vv.y, vv.z, vv.w};
            float p0 = S[(tb * 4 + 0) * 52 + s];
            float p1 = S[(tb * 4 + 1) * 52 + s];
            float p2 = S[(tb * 4 + 2) * 52 + s];
            float p3 = S[(tb * 4 + 3) * 52 + s];
            #pragma unroll
            for (int j = 0; j < 4; j++) {
                acc[0][j] = fmaf(p0, va[j], acc[0][j]);
                acc[1][j] = fmaf(p1, va[j], acc[1][j]);
                acc[2][j] = fmaf(p2, va[j], acc[2][j]);
                acc[3][j] = fmaf(p3, va[j], acc[3][j]);
            }
        }
        #pragma unroll
        for (int i = 0; i < 4; i++) {
            int t = tb * 4 + i;
            if (t >= T) break;
            size_t o = (size_t)(bn * T + t) * CDIM + head * DH + db * 4;
            __nv_bfloat16 h0,h1,h2,h3,l0,l1,l2,l3;
            split_bf16(acc[i][0], h0, l0);
            split_bf16(acc[i][1], h1, l1);
            split_bf16(acc[i][2], h2, l2);
            split_bf16(acc[i][3], h3, l3);
            *(__nv_bfloat162*)(g_att_hi + o)     = __nv_bfloat162{h0,h1};
            *(__nv_bfloat162*)(g_att_hi + o + 2) = __nv_bfloat162{h2,h3};
            *(__nv_bfloat162*)(g_att_lo + o)     = __nv_bfloat162{l0,l1};
            *(__nv_bfloat162*)(g_att_lo + o + 2) = __nv_bfloat162{l2,l3};
        }
    }
}

// ---------------------------------------------------------------------------
extern "C" void kernel_launch(void* const* d_in, const int* in_sizes, int n_in,
                              void* d_out, int out_size)
{
    const float* x     = (const float*)d_in[0];
    const float* wqkv  = (const float*)d_in[1];
    const float* bqkv  = (const float*)d_in[2];
    const float* wproj = (const float*)d_in[3];
    const float* bproj = (const float*)d_in[4];
    const float* table = (const float*)d_in[5];
    float* out = (float*)d_out;

    cudaFuncSetAttribute(gemm_mma<0>, cudaFuncAttributeMaxDynamicSharedMemorySize, SMEM_DYN);
    cudaFuncSetAttribute(gemm_mma<1>, cudaFuncAttributeMaxDynamicSharedMemorySize, SMEM_DYN);

    __nv_bfloat16 *wq_hi, *wq_lo, *wp_hi, *wp_lo;
    cudaGetSymbolAddress((void**)&wq_hi, g_wq_hi);
    cudaGetSymbolAddress((void**)&wq_lo, g_wq_lo);
    cudaGetSymbolAddress((void**)&wp_hi, g_wp_hi);
    cudaGetSymbolAddress((void**)&wp_lo, g_wp_lo);

    gather_convert_x<<<(MROWS * (CDIM/4) + 255) / 256, 256>>>(x);
    convert_w<<<(NQKV * CDIM / 4 + 255) / 256, 256>>>(wqkv,  wq_hi, wq_lo, NQKV * CDIM / 4);
    convert_w<<<(CDIM * CDIM / 4 + 255) / 256, 256>>>(wproj, wp_hi, wp_lo, CDIM * CDIM / 4);

    dim3 g1(NQKV / 128, MROWS / 128);     // (9, 784)
    gemm_mma<0><<<g1, 256, SMEM_DYN>>>(bqkv, nullptr);

    attn_kernel<<<BN * NH, 256>>>(table);

    dim3 g2(CDIM / 128, MROWS / 128);     // (3, 784)
    gemm_mma<1><<<g2, 256, SMEM_DYN>>>(bproj, out);
}

// round 5
// speedup vs baseline: 1.1092x; 1.1092x over previous
#include <cuda_runtime.h>
#include <cuda_bf16.h>
#include <cstdint>

// ---------------- Problem constants ----------------
#define BATCH   32
#define HW      56
#define CDIM    384
#define NH      12
#define DH      32
#define WS      7
#define T       49
#define NWIN    64
#define BN      (BATCH*NWIN)       // 2048
#define MROWS   (BN*T)             // 100352
#define NQKV    (3*CDIM)           // 1152
#define SCALE   0.17677669529663687f

// ---------------- Scratch (static device memory) ----------------
__device__ float          g_qkv[(size_t)BN * NH * 3 * T * DH];     // attn input, fp32
__device__ __nv_bfloat16  g_xw_hi[(size_t)MROWS * CDIM];
__device__ __nv_bfloat16  g_xw_lo[(size_t)MROWS * CDIM];
__device__ __nv_bfloat16  g_att_hi[(size_t)MROWS * CDIM];
__device__ __nv_bfloat16  g_att_lo[(size_t)MROWS * CDIM];
__device__ __nv_bfloat16  g_wq_hi[(size_t)NQKV * CDIM];
__device__ __nv_bfloat16  g_wq_lo[(size_t)NQKV * CDIM];
__device__ __nv_bfloat16  g_wp_hi[(size_t)CDIM * CDIM];
__device__ __nv_bfloat16  g_wp_lo[(size_t)CDIM * CDIM];

// ---------------- helpers ----------------
__device__ __forceinline__ uint32_t smem_u32(const void* p) {
    uint32_t a;
    asm("{ .reg .u64 t; cvta.to.shared.u64 t, %1; cvt.u32.u64 %0, t; }" : "=r"(a) : "l"(p));
    return a;
}

__device__ __forceinline__ void ldsm_x4(uint32_t& r0, uint32_t& r1, uint32_t& r2, uint32_t& r3,
                                        uint32_t addr) {
    asm volatile("ldmatrix.sync.aligned.m8n8.x4.shared.b16 {%0,%1,%2,%3}, [%4];"
                 : "=r"(r0), "=r"(r1), "=r"(r2), "=r"(r3) : "r"(addr));
}

__device__ __forceinline__ void mma_bf16(float* c, const uint32_t* a, uint32_t b0, uint32_t b1) {
    asm volatile(
        "mma.sync.aligned.m16n8k16.row.col.f32.bf16.bf16.f32 "
        "{%0,%1,%2,%3}, {%4,%5,%6,%7}, {%8,%9}, {%0,%1,%2,%3};"
        : "+f"(c[0]), "+f"(c[1]), "+f"(c[2]), "+f"(c[3])
        : "r"(a[0]), "r"(a[1]), "r"(a[2]), "r"(a[3]), "r"(b0), "r"(b1));
}

__device__ __forceinline__ void cp16(uint32_t dst, const void* src) {
    asm volatile("cp.async.cg.shared.global [%0], [%1], 16;" :: "r"(dst), "l"(src));
}

__device__ __forceinline__ void split_bf16(float v, __nv_bfloat16& h, __nv_bfloat16& l) {
    h = __float2bfloat16_rn(v);
    l = __float2bfloat16_rn(v - __bfloat162float(h));
}

// ---------------------------------------------------------------------------
// Precompute 1: gather x (roll -3, window partition) -> bf16 hi/lo [MROWS,384]
// ---------------------------------------------------------------------------
__global__ __launch_bounds__(256)
void gather_convert_x(const float* __restrict__ x)
{
    int idx = blockIdx.x * 256 + threadIdx.x;
    if (idx >= MROWS * (CDIM / 4)) return;
    int row = idx / (CDIM / 4);
    int c4  = idx % (CDIM / 4);
    int bn = row / T, t = row % T;
    int b = bn >> 6, win = bn & 63;
    int wr = win >> 3, wc = win & 7;
    int tr = t / WS, tc = t % WS;
    int h = wr * WS + tr + 3; if (h >= HW) h -= HW;
    int w = wc * WS + tc + 3; if (w >= HW) w -= HW;
    float4 v = *(const float4*)(x + ((size_t)((b * HW + h) * HW + w)) * CDIM + c4 * 4);
    __nv_bfloat16 h0,h1,h2,h3,l0,l1,l2,l3;
    split_bf16(v.x,h0,l0); split_bf16(v.y,h1,l1); split_bf16(v.z,h2,l2); split_bf16(v.w,h3,l3);
    size_t o = (size_t)row * CDIM + c4 * 4;
    *(__nv_bfloat162*)(g_xw_hi + o)     = __nv_bfloat162{h0,h1};
    *(__nv_bfloat162*)(g_xw_hi + o + 2) = __nv_bfloat162{h2,h3};
    *(__nv_bfloat162*)(g_xw_lo + o)     = __nv_bfloat162{l0,l1};
    *(__nv_bfloat162*)(g_xw_lo + o + 2) = __nv_bfloat162{l2,l3};
}

// ---------------------------------------------------------------------------
// Precompute 2: fp32 -> bf16 hi/lo (weights)
// ---------------------------------------------------------------------------
__global__ __launch_bounds__(256)
void convert_w(const float* __restrict__ src, __nv_bfloat16* __restrict__ hi,
               __nv_bfloat16* __restrict__ lo, int n4)
{
    int idx = blockIdx.x * 256 + threadIdx.x;
    if (idx >= n4) return;
    float4 v = *(const float4*)(src + (size_t)idx * 4);
    __nv_bfloat16 h0,h1,h2,h3,l0,l1,l2,l3;
    split_bf16(v.x,h0,l0); split_bf16(v.y,h1,l1); split_bf16(v.z,h2,l2); split_bf16(v.w,h3,l3);
    size_t o = (size_t)idx * 4;
    *(__nv_bfloat162*)(hi + o)     = __nv_bfloat162{h0,h1};
    *(__nv_bfloat162*)(hi + o + 2) = __nv_bfloat162{h2,h3};
    *(__nv_bfloat162*)(lo + o)     = __nv_bfloat162{l0,l1};
    *(__nv_bfloat162*)(lo + o + 2) = __nv_bfloat162{l2,l3};
}

// ---------------------------------------------------------------------------
// mma.sync GEMM, 3-stage cp.async pipeline, ONE __syncthreads per chunk.
// C[128,128] = A[128,384] @ B[128,384]^T  (bf16 hi/lo x3)
// Swizzled smem (no padding): rows of 64B, 16B line l at (l ^ ((row>>1)&3)).
// 8 warps, warp tile 64x32 (warp grid 2x4), BK=32.
// ---------------------------------------------------------------------------
#define TEN_BYTES  (128 * 64)           // 8192 B per tensor (128 rows x 64 B)
#define STG_BYTES  (4 * TEN_BYTES)      // 32768 B per stage
#define NSTAGE     3
#define SMEM_DYN   (NSTAGE * STG_BYTES) // 98304 B
#define NKIT       (CDIM / 32)          // 12

__device__ __forceinline__ uint32_t swz_off(int row, int line) {
    return (uint32_t)(row * 64 + ((line ^ ((row >> 1) & 3)) << 4));
}

template<int MODE>
__global__ __launch_bounds__(256)
void gemm_mma(const float* __restrict__ bias, float* __restrict__ out)
{
    extern __shared__ __align__(16) char dynsmem[];
    const uint32_t u0 = smem_u32(dynsmem);

    const __nv_bfloat16* __restrict__ a_hi = (MODE == 0) ? g_xw_hi : g_att_hi;
    const __nv_bfloat16* __restrict__ a_lo = (MODE == 0) ? g_xw_lo : g_att_lo;
    const __nv_bfloat16* __restrict__ b_hi = (MODE == 0) ? g_wq_hi : g_wp_hi;
    const __nv_bfloat16* __restrict__ b_lo = (MODE == 0) ? g_wq_lo : g_wp_lo;

    const int tid  = threadIdx.x;
    const int lane = tid & 31;
    const int wid  = tid >> 5;
    const int wm   = wid & 1;
    const int wn   = wid >> 1;
    const int mbase = blockIdx.y * 128;
    const int nbase = blockIdx.x * 128;

    float acc[4][4][4];
    #pragma unroll
    for (int i = 0; i < 4; i++)
        #pragma unroll
        for (int j = 0; j < 4; j++)
            #pragma unroll
            for (int k = 0; k < 4; k++) acc[i][j][k] = 0.f;

    // gmem/smem line mapping for cp.async: 2 lines per thread per tensor
    const int r0g = tid >> 2, q0g = tid & 3;   // rows 0..63, line 0..3
    const int r1g = r0g + 64;                  // rows 64..127
    const uint32_t s0 = swz_off(r0g, q0g);
    const uint32_t s1 = swz_off(r1g, q0g);

    auto issue = [&](int st, int k0) {
        uint32_t base = u0 + st * STG_BYTES;
        size_t a0 = (size_t)(mbase + r0g) * CDIM + k0 + q0g * 8;
        size_t a1 = a0 + (size_t)64 * CDIM;
        size_t b0 = (size_t)(nbase + r0g) * CDIM + k0 + q0g * 8;
        size_t b1 = b0 + (size_t)64 * CDIM;
        cp16(base + s0,                 a_hi + a0);
        cp16(base + s1,                 a_hi + a1);
        cp16(base + TEN_BYTES + s0,     a_lo + a0);
        cp16(base + TEN_BYTES + s1,     a_lo + a1);
        cp16(base + 2*TEN_BYTES + s0,   b_hi + b0);
        cp16(base + 2*TEN_BYTES + s1,   b_hi + b1);
        cp16(base + 3*TEN_BYTES + s0,   b_lo + b0);
        cp16(base + 3*TEN_BYTES + s1,   b_lo + b1);
        asm volatile("cp.async.commit_group;");
    };

    // ldmatrix lane addressing (swizzle-aware)
    const int rA  = wm * 64 + (lane & 15);               // +mt*16 keeps swizzle bits
    const int cA0 = lane >> 4;                           // 0/1
    const int sxA = (rA >> 1) & 3;
    const int rB  = wn * 32 + (lane & 7) + (((lane >> 4) & 1) << 3);
    const int cB0 = (lane >> 3) & 1;
    const int sxB = (rB >> 1) & 3;
    const uint32_t aBase = (uint32_t)(rA * 64);
    const uint32_t bBase = (uint32_t)(rB * 64);

    // Prologue: fill stages 0,1
    issue(0, 0);
    issue(1, 32);

    int stage = 0;
    for (int it = 0; it < NKIT; it++) {
        asm volatile("cp.async.wait_group 1;");
        __syncthreads();

        // Issue chunk it+2 into stage (it+2)%3 == (it-1)%3 (freed by the sync above)
        if (it + 2 < NKIT) {
            int st2 = stage + 2; if (st2 >= NSTAGE) st2 -= NSTAGE;
            issue(st2, (it + 2) * 32);
        }

        const uint32_t uAh = u0 + stage * STG_BYTES;
        const uint32_t uAl = uAh + TEN_BYTES;
        const uint32_t uBh = uAh + 2 * TEN_BYTES;
        const uint32_t uBl = uAh + 3 * TEN_BYTES;

        #pragma unroll
        for (int ks = 0; ks < 2; ks++) {
            const uint32_t aOff = aBase + (uint32_t)(((2*ks + cA0) ^ sxA) << 4);
            const uint32_t bOff = bBase + (uint32_t)(((2*ks + cB0) ^ sxB) << 4);
            uint32_t ah[4][4], al[4][4];
            #pragma unroll
            for (int mt = 0; mt < 4; mt++) {
                uint32_t off = aOff + (uint32_t)(mt * 1024);
                ldsm_x4(ah[mt][0], ah[mt][1], ah[mt][2], ah[mt][3], uAh + off);
                ldsm_x4(al[mt][0], al[mt][1], al[mt][2], al[mt][3], uAl + off);
            }
            uint32_t bh[8], bl[8];
            #pragma unroll
            for (int nt2 = 0; nt2 < 2; nt2++) {
                uint32_t off = bOff + (uint32_t)(nt2 * 1024);
                ldsm_x4(bh[nt2*4+0], bh[nt2*4+1], bh[nt2*4+2], bh[nt2*4+3], uBh + off);
                ldsm_x4(bl[nt2*4+0], bl[nt2*4+1], bl[nt2*4+2], bl[nt2*4+3], uBl + off);
            }
            #pragma unroll
            for (int mt = 0; mt < 4; mt++)
                #pragma unroll
                for (int nt = 0; nt < 4; nt++) {
                    uint32_t B0h = bh[nt*2+0], B1h = bh[nt*2+1];
                    uint32_t B0l = bl[nt*2+0], B1l = bl[nt*2+1];
                    mma_bf16(acc[mt][nt], ah[mt], B0h, B1h);
                    mma_bf16(acc[mt][nt], ah[mt], B0l, B1l);
                    mma_bf16(acc[mt][nt], al[mt], B0h, B1h);
                }
        }
        stage++; if (stage >= NSTAGE) stage -= NSTAGE;
    }

    // ---- Epilogue ----
    #pragma unroll
    for (int mt = 0; mt < 4; mt++) {
        #pragma unroll
        for (int hf = 0; hf < 2; hf++) {
            int m = mbase + wm * 64 + mt * 16 + (lane >> 2) + hf * 8;
            int bn = m / T, t = m % T;
            if (MODE == 0) {
                #pragma unroll
                for (int nt = 0; nt < 4; nt++) {
                    int col = nbase + wn * 32 + nt * 8 + (lane & 3) * 2;
                    int which = col / CDIM;
                    int rem   = col - which * CDIM;
                    int head  = rem >> 5;
                    int d     = rem & 31;
                    float2 v;
                    v.x = acc[mt][nt][hf*2+0] + __ldg(&bias[col]);
                    v.y = acc[mt][nt][hf*2+1] + __ldg(&bias[col+1]);
                    *(float2*)(g_qkv + ((size_t)(bn * NH + head) * 3 + which) * (T * DH)
                               + t * DH + d) = v;
                }
            } else {
                int b = bn >> 6, win = bn & 63;
                int wr = win >> 3, wc = win & 7;
                int tr = t / WS, tc = t % WS;
                int h = wr * WS + tr + 3; if (h >= HW) h -= HW;
                int w = wc * WS + tc + 3; if (w >= HW) w -= HW;
                float* orow = out + ((size_t)((b * HW + h) * HW + w)) * CDIM;
                #pragma unroll
                for (int nt = 0; nt < 4; nt++) {
                    int col = nbase + wn * 32 + nt * 8 + (lane & 3) * 2;
                    float2 v;
                    v.x = acc[mt][nt][hf*2+0] + __ldg(&bias[col]);
                    v.y = acc[mt][nt][hf*2+1] + __ldg(&bias[col+1]);
                    *(float2*)(orow + col) = v;
                }
            }
        }
    }
}

// ---------------------------------------------------------------------------
// Attention: block per (window, head). Register-tiled 4x4, float4 LDS.
// ---------------------------------------------------------------------------
__global__ __launch_bounds__(256)
void attn_kernel(const float* __restrict__ table)
{
    const int bnh  = blockIdx.x;
    const int bn   = bnh / NH;
    const int head = bnh % NH;
    const int tid  = threadIdx.x;

    __shared__ __align__(16) float qT[32 * 52];
    __shared__ __align__(16) float kT[32 * 52];
    __shared__ __align__(16) float vs[49 * 32];
    __shared__ __align__(16) float S[52 * 52];
    __shared__ int rid[64];

    const float* base = g_qkv + (size_t)(bn * NH + head) * (3 * T * DH);
    for (int i = tid; i < 3 * T * DH; i += 256) {
        int sec = i / (T * DH);
        int rem = i - sec * (T * DH);
        int t = rem >> 5, d = rem & 31;
        float v = base[i];
        if      (sec == 0) qT[d * 52 + t] = v;
        else if (sec == 1) kT[d * 52 + t] = v;
        else               vs[t * 32 + d] = v;
    }
    if (tid < T) {
        int win = bn & 63;
        int wr = win >> 3, wc = win & 7;
        int tr = tid / WS, tc = tid % WS;
        int h = wr * WS + tr;
        int w = wc * WS + tc;
        int rh = (h < 49) ? 0 : ((h < 53) ? 1 : 2);
        int rw = (w < 49) ? 0 : ((w < 53) ? 1 : 2);
        rid[tid] = rh * 3 + rw;
    }
    __syncthreads();

    for (int task = tid; task < 169; task += 256) {
        int tb = task / 13, sbk = task % 13;
        float acc[4][4];
        #pragma unroll
        for (int i = 0; i < 4; i++)
            #pragma unroll
            for (int j = 0; j < 4; j++) acc[i][j] = 0.f;
        #pragma unroll
        for (int d = 0; d < 32; d++) {
            float4 qv = *(const float4*)&qT[d * 52 + tb * 4];
            float4 kv = *(const float4*)&kT[d * 52 + sbk * 4];
            float qa[4] = {qv.x, qv.y, qv.z, qv.w};
            float ka[4] = {kv.x, kv.y, kv.z, kv.w};
            #pragma unroll
            for (int i = 0; i < 4; i++)
                #pragma unroll
                for (int j = 0; j < 4; j++)
                    acc[i][j] = fmaf(qa[i], ka[j], acc[i][j]);
        }
        #pragma unroll
        for (int i = 0; i < 4; i++) {
            int t = tb * 4 + i;
            if (t >= T) break;
            int tr = t / WS, tcc = t % WS;
            #pragma unroll
            for (int j = 0; j < 4; j++) {
                int s = sbk * 4 + j;
                if (s >= T) continue;
                int sr = s / WS, sc = s % WS;
                float val = acc[i][j] * SCALE;
                int idx = (tr - sr + 6) * 13 + (tcc - sc + 6);
                val += __ldg(&table[idx * NH + head]);
                if (rid[t] != rid[s]) val -= 100.0f;
                S[t * 52 + s] = val;
            }
        }
    }
    __syncthreads();

    if (tid < T) {
        float mx = -1e30f;
        #pragma unroll 7
        for (int s = 0; s < T; s++) mx = fmaxf(mx, S[tid * 52 + s]);
        float sum = 0.f;
        #pragma unroll 7
        for (int s = 0; s < T; s++) {
            float e = __expf(S[tid * 52 + s] - mx);
            S[tid * 52 + s] = e;
            sum += e;
        }
        float inv = 1.0f / sum;
        #pragma unroll 7
        for (int s = 0; s < T; s++) S[tid * 52 + s] *= inv;
    }
    __syncthreads();

    for (int task = tid; task < 13 * 8; task += 256) {
        int tb = task / 8, db = task % 8;
        float acc[4][4];
        #pragma unroll
        for (int i = 0; i < 4; i++)
            #pragma unroll
            for (int j = 0; j < 4; j++) acc[i][j] = 0.f;
        for (int s = 0; s < T; s++) {
            float4 vv = *(const float4*)&vs[s * 32 + db * 4];
            float va[4] = {vv.x, vv.y, vv.z, vv.w};
            float p0 = S[(tb * 4 + 0) * 52 + s];
            float p1 = S[(tb * 4 + 1) * 52 + s];
            float p2 = S[(tb * 4 + 2) * 52 + s];
            float p3 = S[(tb * 4 + 3) * 52 + s];
            #pragma unroll
            for (int j = 0; j < 4; j++) {
                acc[0][j] = fmaf(p0, va[j], acc[0][j]);
                acc[1][j] = fmaf(p1, va[j], acc[1][j]);
                acc[2][j] = fmaf(p2, va[j], acc[2][j]);
                acc[3][j] = fmaf(p3, va[j], acc[3][j]);
            }
        }
        #pragma unroll
        for (int i = 0; i < 4; i++) {
            int t = tb * 4 + i;
            if (t >= T) break;
            size_t o = (size_t)(bn * T + t) * CDIM + head * DH + db * 4;
            __nv_bfloat16 h0,h1,h2,h3,l0,l1,l2,l3;
            split_bf16(acc[i][0], h0, l0);
            split_bf16(acc[i][1], h1, l1);
            split_bf16(acc[i][2], h2, l2);
            split_bf16(acc[i][3], h3, l3);
            *(__nv_bfloat162*)(g_att_hi + o)     = __nv_bfloat162{h0,h1};
            *(__nv_bfloat162*)(g_att_hi + o + 2) = __nv_bfloat162{h2,h3};
            *(__nv_bfloat162*)(g_att_lo + o)     = __nv_bfloat162{l0,l1};
            *(__nv_bfloat162*)(g_att_lo + o + 2) = __nv_bfloat162{l2,l3};
        }
    }
}

// ---------------------------------------------------------------------------
extern "C" void kernel_launch(void* const* d_in, const int* in_sizes, int n_in,
                              void* d_out, int out_size)
{
    const float* x     = (const float*)d_in[0];
    const float* wqkv  = (const float*)d_in[1];
    const float* bqkv  = (const float*)d_in[2];
    const float* wproj = (const float*)d_in[3];
    const float* bproj = (const float*)d_in[4];
    const float* table = (const float*)d_in[5];
    float* out = (float*)d_out;

    cudaFuncSetAttribute(gemm_mma<0>, cudaFuncAttributeMaxDynamicSharedMemorySize, SMEM_DYN);
    cudaFuncSetAttribute(gemm_mma<1>, cudaFuncAttributeMaxDynamicSharedMemorySize, SMEM_DYN);

    __nv_bfloat16 *wq_hi, *wq_lo, *wp_hi, *wp_lo;
    cudaGetSymbolAddress((void**)&wq_hi, g_wq_hi);
    cudaGetSymbolAddress((void**)&wq_lo, g_wq_lo);
    cudaGetSymbolAddress((void**)&wp_hi, g_wp_hi);
    cudaGetSymbolAddress((void**)&wp_lo, g_wp_lo);

    gather_convert_x<<<(MROWS * (CDIM/4) + 255) / 256, 256>>>(x);
    convert_w<<<(NQKV * CDIM / 4 + 255) / 256, 256>>>(wqkv,  wq_hi, wq_lo, NQKV * CDIM / 4);
    convert_w<<<(CDIM * CDIM / 4 + 255) / 256, 256>>>(wproj, wp_hi, wp_lo, CDIM * CDIM / 4);

    dim3 g1(NQKV / 128, MROWS / 128);     // (9, 784)
    gemm_mma<0><<<g1, 256, SMEM_DYN>>>(bqkv, nullptr);

    attn_kernel<<<BN * NH, 256>>>(table);

    dim3 g2(CDIM / 128, MROWS / 128);     // (3, 784)
    gemm_mma<1><<<g2, 256, SMEM_DYN>>>(bproj, out);
}

// round 6
// speedup vs baseline: 1.2086x; 1.0896x over previous
#include <cuda_runtime.h>
#include <cuda_bf16.h>
#include <cstdint>

// ---------------- Problem constants ----------------
#define BATCH   32
#define HW      56
#define CDIM    384
#define NH      12
#define DH      32
#define WS      7
#define T       49
#define NWIN    64
#define BN      (BATCH*NWIN)       // 2048
#define MROWS   (BN*T)             // 100352
#define NQKV    (3*CDIM)           // 1152
#define SCALE   0.17677669529663687f

// ---------------- Scratch (static device memory) ----------------
__device__ float          g_qkv[(size_t)BN * NH * 3 * T * DH];     // attn input, fp32
__device__ __nv_bfloat16  g_xw_hi[(size_t)MROWS * CDIM];
__device__ __nv_bfloat16  g_xw_lo[(size_t)MROWS * CDIM];
__device__ __nv_bfloat16  g_att_hi[(size_t)MROWS * CDIM];
__device__ __nv_bfloat16  g_att_lo[(size_t)MROWS * CDIM];
__device__ __nv_bfloat16  g_wq_hi[(size_t)NQKV * CDIM];
__device__ __nv_bfloat16  g_wq_lo[(size_t)NQKV * CDIM];
__device__ __nv_bfloat16  g_wp_hi[(size_t)CDIM * CDIM];
__device__ __nv_bfloat16  g_wp_lo[(size_t)CDIM * CDIM];

// ---------------- helpers ----------------
__device__ __forceinline__ uint32_t smem_u32(const void* p) {
    uint32_t a;
    asm("{ .reg .u64 t; cvta.to.shared.u64 t, %1; cvt.u32.u64 %0, t; }" : "=r"(a) : "l"(p));
    return a;
}

__device__ __forceinline__ void ldsm_x4(uint32_t& r0, uint32_t& r1, uint32_t& r2, uint32_t& r3,
                                        uint32_t addr) {
    asm volatile("ldmatrix.sync.aligned.m8n8.x4.shared.b16 {%0,%1,%2,%3}, [%4];"
                 : "=r"(r0), "=r"(r1), "=r"(r2), "=r"(r3) : "r"(addr));
}

__device__ __forceinline__ void mma_bf16(float* c, const uint32_t* a, uint32_t b0, uint32_t b1) {
    asm volatile(
        "mma.sync.aligned.m16n8k16.row.col.f32.bf16.bf16.f32 "
        "{%0,%1,%2,%3}, {%4,%5,%6,%7}, {%8,%9}, {%0,%1,%2,%3};"
        : "+f"(c[0]), "+f"(c[1]), "+f"(c[2]), "+f"(c[3])
        : "r"(a[0]), "r"(a[1]), "r"(a[2]), "r"(a[3]), "r"(b0), "r"(b1));
}

__device__ __forceinline__ void cp16(uint32_t dst, const void* src) {
    asm volatile("cp.async.cg.shared.global [%0], [%1], 16;" :: "r"(dst), "l"(src));
}

__device__ __forceinline__ void split_bf16(float v, __nv_bfloat16& h, __nv_bfloat16& l) {
    h = __float2bfloat16_rn(v);
    l = __float2bfloat16_rn(v - __bfloat162float(h));
}

// ---------------------------------------------------------------------------
// Precompute 1: gather x (roll -3, window partition) -> bf16 hi/lo [MROWS,384]
// ---------------------------------------------------------------------------
__global__ __launch_bounds__(256)
void gather_convert_x(const float* __restrict__ x)
{
    int idx = blockIdx.x * 256 + threadIdx.x;
    if (idx >= MROWS * (CDIM / 4)) return;
    int row = idx / (CDIM / 4);
    int c4  = idx % (CDIM / 4);
    int bn = row / T, t = row % T;
    int b = bn >> 6, win = bn & 63;
    int wr = win >> 3, wc = win & 7;
    int tr = t / WS, tc = t % WS;
    int h = wr * WS + tr + 3; if (h >= HW) h -= HW;
    int w = wc * WS + tc + 3; if (w >= HW) w -= HW;
    float4 v = *(const float4*)(x + ((size_t)((b * HW + h) * HW + w)) * CDIM + c4 * 4);
    __nv_bfloat16 h0,h1,h2,h3,l0,l1,l2,l3;
    split_bf16(v.x,h0,l0); split_bf16(v.y,h1,l1); split_bf16(v.z,h2,l2); split_bf16(v.w,h3,l3);
    size_t o = (size_t)row * CDIM + c4 * 4;
    *(__nv_bfloat162*)(g_xw_hi + o)     = __nv_bfloat162{h0,h1};
    *(__nv_bfloat162*)(g_xw_hi + o + 2) = __nv_bfloat162{h2,h3};
    *(__nv_bfloat162*)(g_xw_lo + o)     = __nv_bfloat162{l0,l1};
    *(__nv_bfloat162*)(g_xw_lo + o + 2) = __nv_bfloat162{l2,l3};
}

// ---------------------------------------------------------------------------
// Precompute 2: fp32 -> bf16 hi/lo (weights)
// ---------------------------------------------------------------------------
__global__ __launch_bounds__(256)
void convert_w(const float* __restrict__ src, __nv_bfloat16* __restrict__ hi,
               __nv_bfloat16* __restrict__ lo, int n4)
{
    int idx = blockIdx.x * 256 + threadIdx.x;
    if (idx >= n4) return;
    float4 v = *(const float4*)(src + (size_t)idx * 4);
    __nv_bfloat16 h0,h1,h2,h3,l0,l1,l2,l3;
    split_bf16(v.x,h0,l0); split_bf16(v.y,h1,l1); split_bf16(v.z,h2,l2); split_bf16(v.w,h3,l3);
    size_t o = (size_t)idx * 4;
    *(__nv_bfloat162*)(hi + o)     = __nv_bfloat162{h0,h1};
    *(__nv_bfloat162*)(hi + o + 2) = __nv_bfloat162{h2,h3};
    *(__nv_bfloat162*)(lo + o)     = __nv_bfloat162{l0,l1};
    *(__nv_bfloat162*)(lo + o + 2) = __nv_bfloat162{l2,l3};
}

// ---------------------------------------------------------------------------
// mma.sync GEMM, 3-stage cp.async pipeline, ONE __syncthreads per chunk.
// C[128,128] = A[128,384] @ B[128,384]^T  (bf16 hi/lo x3)
// Swizzled smem (no padding): rows of 64B, 16B line l at (l ^ ((row>>1)&3)).
// 8 warps, warp tile 64x32 (warp grid 2x4), BK=32.
// ---------------------------------------------------------------------------
#define TEN_BYTES  (128 * 64)           // 8192 B per tensor (128 rows x 64 B)
#define STG_BYTES  (4 * TEN_BYTES)      // 32768 B per stage
#define NSTAGE     3
#define SMEM_DYN   (NSTAGE * STG_BYTES) // 98304 B
#define NKIT       (CDIM / 32)          // 12

__device__ __forceinline__ uint32_t swz_off(int row, int line) {
    return (uint32_t)(row * 64 + ((line ^ ((row >> 1) & 3)) << 4));
}

template<int MODE>
__global__ __launch_bounds__(256)
void gemm_mma(const float* __restrict__ bias, float* __restrict__ out)
{
    extern __shared__ __align__(16) char dynsmem[];
    const uint32_t u0 = smem_u32(dynsmem);

    const __nv_bfloat16* __restrict__ a_hi = (MODE == 0) ? g_xw_hi : g_att_hi;
    const __nv_bfloat16* __restrict__ a_lo = (MODE == 0) ? g_xw_lo : g_att_lo;
    const __nv_bfloat16* __restrict__ b_hi = (MODE == 0) ? g_wq_hi : g_wp_hi;
    const __nv_bfloat16* __restrict__ b_lo = (MODE == 0) ? g_wq_lo : g_wp_lo;

    const int tid  = threadIdx.x;
    const int lane = tid & 31;
    const int wid  = tid >> 5;
    const int wm   = wid & 1;
    const int wn   = wid >> 1;
    const int mbase = blockIdx.y * 128;
    const int nbase = blockIdx.x * 128;

    float acc[4][4][4];
    #pragma unroll
    for (int i = 0; i < 4; i++)
        #pragma unroll
        for (int j = 0; j < 4; j++)
            #pragma unroll
            for (int k = 0; k < 4; k++) acc[i][j][k] = 0.f;

    // gmem/smem line mapping for cp.async: 2 lines per thread per tensor
    const int r0g = tid >> 2, q0g = tid & 3;   // rows 0..63, line 0..3
    const int r1g = r0g + 64;                  // rows 64..127
    const uint32_t s0 = swz_off(r0g, q0g);
    const uint32_t s1 = swz_off(r1g, q0g);

    auto issue = [&](int st, int k0) {
        uint32_t base = u0 + st * STG_BYTES;
        size_t a0 = (size_t)(mbase + r0g) * CDIM + k0 + q0g * 8;
        size_t a1 = a0 + (size_t)64 * CDIM;
        size_t b0 = (size_t)(nbase + r0g) * CDIM + k0 + q0g * 8;
        size_t b1 = b0 + (size_t)64 * CDIM;
        cp16(base + s0,                 a_hi + a0);
        cp16(base + s1,                 a_hi + a1);
        cp16(base + TEN_BYTES + s0,     a_lo + a0);
        cp16(base + TEN_BYTES + s1,     a_lo + a1);
        cp16(base + 2*TEN_BYTES + s0,   b_hi + b0);
        cp16(base + 2*TEN_BYTES + s1,   b_hi + b1);
        cp16(base + 3*TEN_BYTES + s0,   b_lo + b0);
        cp16(base + 3*TEN_BYTES + s1,   b_lo + b1);
        asm volatile("cp.async.commit_group;");
    };

    // ldmatrix lane addressing (swizzle-aware)
    const int rA  = wm * 64 + (lane & 15);
    const int cA0 = lane >> 4;
    const int sxA = (rA >> 1) & 3;
    const int rB  = wn * 32 + (lane & 7) + (((lane >> 4) & 1) << 3);
    const int cB0 = (lane >> 3) & 1;
    const int sxB = (rB >> 1) & 3;
    const uint32_t aBase = (uint32_t)(rA * 64);
    const uint32_t bBase = (uint32_t)(rB * 64);

    // Prologue: fill stages 0,1
    issue(0, 0);
    issue(1, 32);

    int stage = 0;
    for (int it = 0; it < NKIT; it++) {
        asm volatile("cp.async.wait_group 1;");
        __syncthreads();

        if (it + 2 < NKIT) {
            int st2 = stage + 2; if (st2 >= NSTAGE) st2 -= NSTAGE;
            issue(st2, (it + 2) * 32);
        }

        const uint32_t uAh = u0 + stage * STG_BYTES;
        const uint32_t uAl = uAh + TEN_BYTES;
        const uint32_t uBh = uAh + 2 * TEN_BYTES;
        const uint32_t uBl = uAh + 3 * TEN_BYTES;

        #pragma unroll
        for (int ks = 0; ks < 2; ks++) {
            const uint32_t aOff = aBase + (uint32_t)(((2*ks + cA0) ^ sxA) << 4);
            const uint32_t bOff = bBase + (uint32_t)(((2*ks + cB0) ^ sxB) << 4);
            uint32_t ah[4][4], al[4][4];
            #pragma unroll
            for (int mt = 0; mt < 4; mt++) {
                uint32_t off = aOff + (uint32_t)(mt * 1024);
                ldsm_x4(ah[mt][0], ah[mt][1], ah[mt][2], ah[mt][3], uAh + off);
                ldsm_x4(al[mt][0], al[mt][1], al[mt][2], al[mt][3], uAl + off);
            }
            uint32_t bh[8], bl[8];
            #pragma unroll
            for (int nt2 = 0; nt2 < 2; nt2++) {
                uint32_t off = bOff + (uint32_t)(nt2 * 1024);
                ldsm_x4(bh[nt2*4+0], bh[nt2*4+1], bh[nt2*4+2], bh[nt2*4+3], uBh + off);
                ldsm_x4(bl[nt2*4+0], bl[nt2*4+1], bl[nt2*4+2], bl[nt2*4+3], uBl + off);
            }
            #pragma unroll
            for (int mt = 0; mt < 4; mt++)
                #pragma unroll
                for (int nt = 0; nt < 4; nt++) {
                    uint32_t B0h = bh[nt*2+0], B1h = bh[nt*2+1];
                    uint32_t B0l = bl[nt*2+0], B1l = bl[nt*2+1];
                    mma_bf16(acc[mt][nt], ah[mt], B0h, B1h);
                    mma_bf16(acc[mt][nt], ah[mt], B0l, B1l);
                    mma_bf16(acc[mt][nt], al[mt], B0h, B1h);
                }
        }
        stage++; if (stage >= NSTAGE) stage -= NSTAGE;
    }

    // ---- Epilogue ----
    #pragma unroll
    for (int mt = 0; mt < 4; mt++) {
        #pragma unroll
        for (int hf = 0; hf < 2; hf++) {
            int m = mbase + wm * 64 + mt * 16 + (lane >> 2) + hf * 8;
            int bn = m / T, t = m % T;
            if (MODE == 0) {
                #pragma unroll
                for (int nt = 0; nt < 4; nt++) {
                    int col = nbase + wn * 32 + nt * 8 + (lane & 3) * 2;
                    int which = col / CDIM;
                    int rem   = col - which * CDIM;
                    int head  = rem >> 5;
                    int d     = rem & 31;
                    float2 v;
                    v.x = acc[mt][nt][hf*2+0] + __ldg(&bias[col]);
                    v.y = acc[mt][nt][hf*2+1] + __ldg(&bias[col+1]);
                    *(float2*)(g_qkv + ((size_t)(bn * NH + head) * 3 + which) * (T * DH)
                               + t * DH + d) = v;
                }
            } else {
                int b = bn >> 6, win = bn & 63;
                int wr = win >> 3, wc = win & 7;
                int tr = t / WS, tc = t % WS;
                int h = wr * WS + tr + 3; if (h >= HW) h -= HW;
                int w = wc * WS + tc + 3; if (w >= HW) w -= HW;
                float* orow = out + ((size_t)((b * HW + h) * HW + w)) * CDIM;
                #pragma unroll
                for (int nt = 0; nt < 4; nt++) {
                    int col = nbase + wn * 32 + nt * 8 + (lane & 3) * 2;
                    float2 v;
                    v.x = acc[mt][nt][hf*2+0] + __ldg(&bias[col]);
                    v.y = acc[mt][nt][hf*2+1] + __ldg(&bias[col+1]);
                    *(float2*)(orow + col) = v;
                }
            }
        }
    }
}

// ---------------------------------------------------------------------------
// Attention: block per (window, head).
// QK^T: 169 tasks of 4x4.  Softmax: warp-parallel (8 warps x rows, shfl).
// PV: 200 tasks of 2x4 (78% util, single pass).
// ---------------------------------------------------------------------------
__global__ __launch_bounds__(256)
void attn_kernel(const float* __restrict__ table)
{
    const int bnh  = blockIdx.x;
    const int bn   = bnh / NH;
    const int head = bnh % NH;
    const int tid  = threadIdx.x;
    const int lane = tid & 31;
    const int wid  = tid >> 5;

    __shared__ __align__(16) float qT[32 * 52];
    __shared__ __align__(16) float kT[32 * 52];
    __shared__ __align__(16) float vs[49 * 32];
    __shared__ __align__(16) float S[52 * 52];
    __shared__ int rid[64];

    const float* base = g_qkv + (size_t)(bn * NH + head) * (3 * T * DH);
    for (int i = tid; i < 3 * T * DH; i += 256) {
        int sec = i / (T * DH);
        int rem = i - sec * (T * DH);
        int t = rem >> 5, d = rem & 31;
        float v = base[i];
        if      (sec == 0) qT[d * 52 + t] = v;
        else if (sec == 1) kT[d * 52 + t] = v;
        else               vs[t * 32 + d] = v;
    }
    if (tid < T) {
        int win = bn & 63;
        int wr = win >> 3, wc = win & 7;
        int tr = tid / WS, tc = tid % WS;
        int h = wr * WS + tr;
        int w = wc * WS + tc;
        int rh = (h < 49) ? 0 : ((h < 53) ? 1 : 2);
        int rw = (w < 49) ? 0 : ((w < 53) ? 1 : 2);
        rid[tid] = rh * 3 + rw;
    }
    __syncthreads();

    // ---- S = scale*QK^T + bias + mask : 169 tasks of 4x4, one pass ----
    if (tid < 169) {
        int tb = tid / 13, sbk = tid % 13;
        float acc[4][4];
        #pragma unroll
        for (int i = 0; i < 4; i++)
            #pragma unroll
            for (int j = 0; j < 4; j++) acc[i][j] = 0.f;
        #pragma unroll
        for (int d = 0; d < 32; d++) {
            float4 qv = *(const float4*)&qT[d * 52 + tb * 4];
            float4 kv = *(const float4*)&kT[d * 52 + sbk * 4];
            float qa[4] = {qv.x, qv.y, qv.z, qv.w};
            float ka[4] = {kv.x, kv.y, kv.z, kv.w};
            #pragma unroll
            for (int i = 0; i < 4; i++)
                #pragma unroll
                for (int j = 0; j < 4; j++)
                    acc[i][j] = fmaf(qa[i], ka[j], acc[i][j]);
        }
        #pragma unroll
        for (int i = 0; i < 4; i++) {
            int t = tb * 4 + i;
            if (t >= T) break;
            int tr = t / WS, tcc = t % WS;
            #pragma unroll
            for (int j = 0; j < 4; j++) {
                int s = sbk * 4 + j;
                if (s >= T) continue;
                int sr = s / WS, sc = s % WS;
                float val = acc[i][j] * SCALE;
                int idx = (tr - sr + 6) * 13 + (tcc - sc + 6);
                val += __ldg(&table[idx * NH + head]);
                if (rid[t] != rid[s]) val -= 100.0f;
                S[t * 52 + s] = val;
            }
        }
    }
    __syncthreads();

    // ---- warp-parallel softmax: warp per row ----
    for (int t = wid; t < T; t += 8) {
        float v0 = S[t * 52 + lane];
        float v1 = (lane < 17) ? S[t * 52 + 32 + lane] : -1e30f;
        float mx = fmaxf(v0, v1);
        #pragma unroll
        for (int off = 16; off > 0; off >>= 1)
            mx = fmaxf(mx, __shfl_xor_sync(0xFFFFFFFFu, mx, off));
        float e0 = __expf(v0 - mx);
        float e1 = (lane < 17) ? __expf(v1 - mx) : 0.f;
        float sum = e0 + e1;
        #pragma unroll
        for (int off = 16; off > 0; off >>= 1)
            sum += __shfl_xor_sync(0xFFFFFFFFu, sum, off);
        float inv = __frcp_rn(sum);
        S[t * 52 + lane] = e0 * inv;
        if (lane < 17) S[t * 52 + 32 + lane] = e1 * inv;
    }
    __syncthreads();

    // ---- out = P @ V : 200 tasks of 2x4, one pass, write bf16 hi/lo ----
    if (tid < 200) {
        int tb = tid >> 3;          // 0..24 -> rows 2tb, 2tb+1
        int db = tid & 7;           // 0..7  -> cols db*4..db*4+3
        int t0 = tb * 2;
        float acc[2][4];
        #pragma unroll
        for (int i = 0; i < 2; i++)
            #pragma unroll
            for (int j = 0; j < 4; j++) acc[i][j] = 0.f;
        for (int s = 0; s < T; s++) {
            float4 vv = *(const float4*)&vs[s * 32 + db * 4];
            float p0 = S[t0 * 52 + s];
            float p1 = S[(t0 + 1) * 52 + s];   // row 49 slot exists (pad), value garbage but guarded below
            acc[0][0] = fmaf(p0, vv.x, acc[0][0]);
            acc[0][1] = fmaf(p0, vv.y, acc[0][1]);
            acc[0][2] = fmaf(p0, vv.z, acc[0][2]);
            acc[0][3] = fmaf(p0, vv.w, acc[0][3]);
            acc[1][0] = fmaf(p1, vv.x, acc[1][0]);
            acc[1][1] = fmaf(p1, vv.y, acc[1][1]);
            acc[1][2] = fmaf(p1, vv.z, acc[1][2]);
            acc[1][3] = fmaf(p1, vv.w, acc[1][3]);
        }
        #pragma unroll
        for (int i = 0; i < 2; i++) {
            int t = t0 + i;
            if (t >= T) break;
            size_t o = (size_t)(bn * T + t) * CDIM + head * DH + db * 4;
            __nv_bfloat16 h0,h1,h2,h3,l0,l1,l2,l3;
            split_bf16(acc[i][0], h0, l0);
            split_bf16(acc[i][1], h1, l1);
            split_bf16(acc[i][2], h2, l2);
            split_bf16(acc[i][3], h3, l3);
            *(__nv_bfloat162*)(g_att_hi + o)     = __nv_bfloat162{h0,h1};
            *(__nv_bfloat162*)(g_att_hi + o + 2) = __nv_bfloat162{h2,h3};
            *(__nv_bfloat162*)(g_att_lo + o)     = __nv_bfloat162{l0,l1};
            *(__nv_bfloat162*)(g_att_lo + o + 2) = __nv_bfloat162{l2,l3};
        }
    }
}

// ---------------------------------------------------------------------------
extern "C" void kernel_launch(void* const* d_in, const int* in_sizes, int n_in,
                              void* d_out, int out_size)
{
    const float* x     = (const float*)d_in[0];
    const float* wqkv  = (const float*)d_in[1];
    const float* bqkv  = (const float*)d_in[2];
    const float* wproj = (const float*)d_in[3];
    const float* bproj = (const float*)d_in[4];
    const float* table = (const float*)d_in[5];
    float* out = (float*)d_out;

    cudaFuncSetAttribute(gemm_mma<0>, cudaFuncAttributeMaxDynamicSharedMemorySize, SMEM_DYN);
    cudaFuncSetAttribute(gemm_mma<1>, cudaFuncAttributeMaxDynamicSharedMemorySize, SMEM_DYN);

    __nv_bfloat16 *wq_hi, *wq_lo, *wp_hi, *wp_lo;
    cudaGetSymbolAddress((void**)&wq_hi, g_wq_hi);
    cudaGetSymbolAddress((void**)&wq_lo, g_wq_lo);
    cudaGetSymbolAddress((void**)&wp_hi, g_wp_hi);
    cudaGetSymbolAddress((void**)&wp_lo, g_wp_lo);

    gather_convert_x<<<(MROWS * (CDIM/4) + 255) / 256, 256>>>(x);
    convert_w<<<(NQKV * CDIM / 4 + 255) / 256, 256>>>(wqkv,  wq_hi, wq_lo, NQKV * CDIM / 4);
    convert_w<<<(CDIM * CDIM / 4 + 255) / 256, 256>>>(wproj, wp_hi, wp_lo, CDIM * CDIM / 4);

    dim3 g1(NQKV / 128, MROWS / 128);     // (9, 784)
    gemm_mma<0><<<g1, 256, SMEM_DYN>>>(bqkv, nullptr);

    attn_kernel<<<BN * NH, 256>>>(table);

    dim3 g2(CDIM / 128, MROWS / 128);     // (3, 784)
    gemm_mma<1><<<g2, 256, SMEM_DYN>>>(bproj, out);
}